// round 16
// baseline (speedup 1.0000x reference)
#include <cuda_runtime.h>
#include <cuda_bf16.h>

// MedianFilter1D: x[16, 64, 16384] fp32, window k=9, zero padding.
// 1024 rows x 16384 = 2,097,152 = 2^21 chunks of 8 outputs.
//
// Round 16 — copy-free exact-tiling pipeline. R15 (shfl-free persistent,
// kernel 18.9us) still burned ~1.2us on the 16-float rolling-buffer copy
// (fma 6.4%) and had ragged 11/12-chunk imbalance. Fix: STRIDE = 2^17
// (TPB=128, GRID=1024) -> exactly 16 chunks/thread, so the double buffer
// alternates structurally in a counted single-exit loop (7 iters x 2 phases
// + peeled epilogue): zero copies, zero guards, zero tail.
// launch_bounds(128,10): all 1024 blocks resident in one wave.
//
// Memory: direct overlapping loads (predicated halo float4s, no shfl),
// st.global.L2::evict_first.v8 stores.
// Compute: sort 7 adjacent pairs; sorted-4 runs via 3-CE merge; ranks 3,4 of
// shared 8 via pruned odd-even merge(4,4); median9 = clamp(inserted, s3, s4).

#define CE(a, b) { float _lo = fminf(a, b); float _hi = fmaxf(a, b); (a) = _lo; (b) = _hi; }

__device__ __forceinline__ void st_out8(float* p, const float* o)
{
    asm volatile(
        "st.global.L2::evict_first.v8.f32 [%0], {%1,%2,%3,%4,%5,%6,%7,%8};"
        :: "l"(p),
           "f"(o[0]), "f"(o[1]), "f"(o[2]), "f"(o[3]),
           "f"(o[4]), "f"(o[5]), "f"(o[6]), "f"(o[7])
        : "memory");
}

static constexpr int L      = 16384;
static constexpr int ROWS   = 16 * 64;
static constexpr int TPB    = 128;
static constexpr int GRID   = 1024;
static constexpr int NCHUNK = ROWS * (L / 8);     // 2,097,152 = 2^21
static constexpr int STRIDE = GRID * TPB;         // 131,072 = 2^17
static constexpr int ITERS  = NCHUNK / STRIDE;    // 16 exactly

// Load the 16-float window for chunk c into v[0..16): [8c-4, 8c+12).
__device__ __forceinline__ void load_window(const float* __restrict__ x, int c, float* v)
{
    const float4* p = reinterpret_cast<const float4*>(x + 8 * (size_t)c);
    int cm = c & 2047;                       // chunk position within row

    float4 a = __ldg(p);                     // [cb, cb+4)
    float4 b = __ldg(p + 1);                 // [cb+4, cb+8)
    float4 lh = (cm != 0)    ? __ldg(p - 1)  // [cb-4, cb)
                             : make_float4(0.f, 0.f, 0.f, 0.f);
    float4 rh = (cm != 2047) ? __ldg(p + 2)  // [cb+8, cb+12)
                             : make_float4(0.f, 0.f, 0.f, 0.f);

    v[0]  = lh.x; v[1]  = lh.y; v[2]  = lh.z; v[3]  = lh.w;
    v[4]  = a.x;  v[5]  = a.y;  v[6]  = a.z;  v[7]  = a.w;
    v[8]  = b.x;  v[9]  = b.y;  v[10] = b.z;  v[11] = b.w;
    v[12] = rh.x; v[13] = rh.y; v[14] = rh.z; v[15] = rh.w;
}

__device__ __forceinline__ void compute_store(
    float* __restrict__ y, const float* v, int c)
{
    // Sorted pairs P_j = sorted(v[2j+1], v[2j+2]), j = 0..6.
    float pl[7], ph[7];
    #pragma unroll
    for (int j = 0; j < 7; j++) {
        pl[j] = fminf(v[2*j + 1], v[2*j + 2]);
        ph[j] = fmaxf(v[2*j + 1], v[2*j + 2]);
    }

    // Runs R[i] = sorted-4 of v[2i+1 .. 2i+5) = merge(P_i, P_{i+1}), 3 CE.
    float R[6][4];
    #pragma unroll
    for (int i = 0; i < 6; i++) {
        float x0 = pl[i], x1 = ph[i], x2 = pl[i + 1], x3 = ph[i + 1];
        CE(x0, x2) CE(x1, x3) CE(x1, x2)
        R[i][0] = x0; R[i][1] = x1; R[i][2] = x2; R[i][3] = x3;
    }

    float o[8];
    #pragma unroll
    for (int j = 0; j < 4; j++) {
        int b = 2 * j;
        const float* A = R[j];       // sorted v[b+1 .. b+5)
        const float* B = R[j + 2];   // sorted v[b+5 .. b+9)
        float e2 = fmaxf(fmaxf(A[0], B[0]), fminf(A[2], B[2]));
        float o1 = fminf(fmaxf(A[1], B[1]), fminf(A[3], B[3]));
        float s3 = fminf(o1, e2);
        float s4 = fmaxf(o1, e2);
        o[b]     = fminf(fmaxf(v[b],     s3), s4);
        o[b + 1] = fminf(fmaxf(v[b + 9], s3), s4);
    }

    st_out8(y + 8 * (size_t)c, o);
}

__global__ __launch_bounds__(TPB, 10)
void median9_kernel(const float* __restrict__ x, float* __restrict__ y)
{
    int t = blockIdx.x * TPB + threadIdx.x;

    static_assert(ITERS == 16, "pipeline assumes exactly 16 chunks/thread");

    float A[16], B[16];
    int c = t;
    load_window(x, c, A);                    // prologue: chunk 0 -> A

    // 7 full A/B alternations (chunks 0..13), single-exit counted loop.
    #pragma unroll 1
    for (int i = 0; i < 7; i++) {
        load_window(x, c + STRIDE, B);       // chunk 2i+1
        compute_store(y, A, c);              // chunk 2i
        load_window(x, c + 2 * STRIDE, A);   // chunk 2i+2
        compute_store(y, B, c + STRIDE);     // chunk 2i+1
        c += 2 * STRIDE;
    }

    // Epilogue: chunks 14 (in A) and 15.
    load_window(x, c + STRIDE, B);
    compute_store(y, A, c);
    compute_store(y, B, c + STRIDE);
}

extern "C" void kernel_launch(void* const* d_in, const int* in_sizes, int n_in,
                              void* d_out, int out_size)
{
    const float* x = (const float*)d_in[0];
    float* y = (float*)d_out;
    median9_kernel<<<GRID, TPB>>>(x, y);
}

// round 17
// speedup vs baseline: 1.0089x; 1.0089x over previous
#include <cuda_runtime.h>
#include <cuda_bf16.h>

// MedianFilter1D: x[16, 64, 16384] fp32, window k=9, zero padding.
// 1024 rows x 16384 = 2,097,152 = 2^21 chunks of 8 outputs.
//
// Round 17 — fully-unrolled flat pipeline. Combines the two validated wins:
//  * R15: shfl-free direct overlapping loads (kernel 18.9us, best)
//  * R16: copy-free buffer alternation (fma 6.4% -> 1.6% validated)
// while avoiding the two failure modes seen: loop-carried copies (R13/R15)
// and multi-exit / ragged-tiling loops (R14/R16). GRID=2048 x TPB=256 ->
// STRIDE = 2^19, ITERS = 4 exactly; the whole pipeline is straight-line:
//   ld0 ld1 | proc0 ld2 | proc1 ld3 | proc2 | proc3
//
// Memory: predicated halo float4 loads (no shfl), st.L2::evict_first.v8.
// Compute: sort 7 adjacent pairs; sorted-4 runs via 3-CE merge; ranks 3,4 of
// shared 8 via pruned odd-even merge(4,4); median9 = clamp(inserted, s3, s4).

#define CE(a, b) { float _lo = fminf(a, b); float _hi = fmaxf(a, b); (a) = _lo; (b) = _hi; }

__device__ __forceinline__ void st_out8(float* p, const float* o)
{
    asm volatile(
        "st.global.L2::evict_first.v8.f32 [%0], {%1,%2,%3,%4,%5,%6,%7,%8};"
        :: "l"(p),
           "f"(o[0]), "f"(o[1]), "f"(o[2]), "f"(o[3]),
           "f"(o[4]), "f"(o[5]), "f"(o[6]), "f"(o[7])
        : "memory");
}

static constexpr int L      = 16384;
static constexpr int ROWS   = 16 * 64;
static constexpr int TPB    = 256;
static constexpr int GRID   = 2048;
static constexpr int NCHUNK = ROWS * (L / 8);     // 2,097,152 = 2^21
static constexpr int STRIDE = GRID * TPB;         // 524,288 = 2^19
static constexpr int ITERS  = NCHUNK / STRIDE;    // 4 exactly

// Load the 16-float window for chunk c into v[0..16): [8c-4, 8c+12).
__device__ __forceinline__ void load_window(const float* __restrict__ x, int c, float* v)
{
    const float4* p = reinterpret_cast<const float4*>(x + 8 * (size_t)c);
    int cm = c & 2047;                       // chunk position within row

    float4 a = __ldg(p);                     // [cb, cb+4)
    float4 b = __ldg(p + 1);                 // [cb+4, cb+8)
    float4 lh = (cm != 0)    ? __ldg(p - 1)  // [cb-4, cb)
                             : make_float4(0.f, 0.f, 0.f, 0.f);
    float4 rh = (cm != 2047) ? __ldg(p + 2)  // [cb+8, cb+12)
                             : make_float4(0.f, 0.f, 0.f, 0.f);

    v[0]  = lh.x; v[1]  = lh.y; v[2]  = lh.z; v[3]  = lh.w;
    v[4]  = a.x;  v[5]  = a.y;  v[6]  = a.z;  v[7]  = a.w;
    v[8]  = b.x;  v[9]  = b.y;  v[10] = b.z;  v[11] = b.w;
    v[12] = rh.x; v[13] = rh.y; v[14] = rh.z; v[15] = rh.w;
}

__device__ __forceinline__ void compute_store(
    float* __restrict__ y, const float* v, int c)
{
    // Sorted pairs P_j = sorted(v[2j+1], v[2j+2]), j = 0..6.
    float pl[7], ph[7];
    #pragma unroll
    for (int j = 0; j < 7; j++) {
        pl[j] = fminf(v[2*j + 1], v[2*j + 2]);
        ph[j] = fmaxf(v[2*j + 1], v[2*j + 2]);
    }

    // Runs R[i] = sorted-4 of v[2i+1 .. 2i+5) = merge(P_i, P_{i+1}), 3 CE.
    float R[6][4];
    #pragma unroll
    for (int i = 0; i < 6; i++) {
        float x0 = pl[i], x1 = ph[i], x2 = pl[i + 1], x3 = ph[i + 1];
        CE(x0, x2) CE(x1, x3) CE(x1, x2)
        R[i][0] = x0; R[i][1] = x1; R[i][2] = x2; R[i][3] = x3;
    }

    float o[8];
    #pragma unroll
    for (int j = 0; j < 4; j++) {
        int b = 2 * j;
        const float* A = R[j];       // sorted v[b+1 .. b+5)
        const float* B = R[j + 2];   // sorted v[b+5 .. b+9)
        float e2 = fmaxf(fmaxf(A[0], B[0]), fminf(A[2], B[2]));
        float o1 = fminf(fmaxf(A[1], B[1]), fminf(A[3], B[3]));
        float s3 = fminf(o1, e2);
        float s4 = fmaxf(o1, e2);
        o[b]     = fminf(fmaxf(v[b],     s3), s4);
        o[b + 1] = fminf(fmaxf(v[b + 9], s3), s4);
    }

    st_out8(y + 8 * (size_t)c, o);
}

__global__ __launch_bounds__(TPB, 4)
void median9_kernel(const float* __restrict__ x, float* __restrict__ y)
{
    int t = blockIdx.x * TPB + threadIdx.x;

    static_assert(ITERS == 4, "flat pipeline assumes exactly 4 chunks/thread");

    int c0 = t;
    int c1 = t + STRIDE;
    int c2 = t + 2 * STRIDE;
    int c3 = t + 3 * STRIDE;

    float A[16], B[16];
    load_window(x, c0, A);        // in flight: A
    load_window(x, c1, B);        // in flight: A, B

    compute_store(y, A, c0);      // consume A
    load_window(x, c2, A);        // refill A

    compute_store(y, B, c1);      // consume B
    load_window(x, c3, B);        // refill B

    compute_store(y, A, c2);
    compute_store(y, B, c3);
}

extern "C" void kernel_launch(void* const* d_in, const int* in_sizes, int n_in,
                              void* d_out, int out_size)
{
    const float* x = (const float*)d_in[0];
    float* y = (float*)d_out;
    median9_kernel<<<GRID, TPB>>>(x, y);
}